// round 12
// baseline (speedup 1.0000x reference)
#include <cuda_runtime.h>

// Swin window attention, fused per-window. 512 threads/CTA (16 warps) for
// latency hiding; all intermediates in smem.
// Inputs (metadata order): x[16384*49*128] f32, mask[256*49*49] f32,
// qkv_w[384*128] f32, qkv_b[384] f32, proj_w[128*128] f32, proj_b[128] f32,
// rpb_table[169*4] f32, rpi[49*49] i32.  Output: [16384*49*128] f32.

#define TOK 49
constexpr int THREADS = 512;

// smem layout (float offsets)
constexpr int XS_OFF  = 0;            // x (49x128), later attention output
constexpr int QS_OFF  = 6272;         // q pre-scaled, row-swizzled
constexpr int KS_OFF  = 12544;
constexpr int VS_OFF  = 18816;
constexpr int WS_OFF  = 25088;        // 128x128 weight chunk (swizzled); reused for scores (4*49*49)
constexpr int RPI_OFF = 41472;        // 2401 int32
constexpr int RPB_OFF = 43873;        // 676 f32
constexpr int SMEM_FLOATS = 44549;
constexpr int SMEM_BYTES  = SMEM_FLOATS * 4;   // 178196 B

__device__ __forceinline__ void fma2(unsigned long long& d, unsigned long long a, unsigned long long b) {
    asm("fma.rn.f32x2 %0, %1, %2, %0;" : "+l"(d) : "l"(a), "l"(b));
}
__device__ __forceinline__ float2 unpk(unsigned long long v) {
    float2 r; asm("mov.b64 {%0, %1}, %2;" : "=f"(r.x), "=f"(r.y) : "l"(v)); return r;
}

// copy a 128x128 f32 weight block (row d contiguous over c) into ws with an
// XOR-4 swizzle so that column-strided LDS.128 reads are bank-conflict-free.
__device__ __forceinline__ void load_wchunk(const float* __restrict__ g, float* ws, int tid) {
    for (int i = tid * 4; i < 16384; i += THREADS * 4) {
        float4 v = *(const float4*)(g + i);
        int d = i >> 7, c = i & 127;
        *(float4*)&ws[(d << 7) + (c ^ (((d >> 1) & 7) << 2))] = v;
    }
}

// out[n][d] = (sum_c A[n][c] * W[d][c] + bias[d]) * mult, n in [0,49), d in [0,128)
// 16 warps: 8 row groups of 7 rows x 2 column halves. 2 output cols per thread.
// A: smem, stride 128, unswizzled.  W: ws (swizzled per load_wchunk).
// TO_GLOBAL: store contiguous to global; else store to smem with row XOR swizzle.
template<bool TO_GLOBAL>
__device__ __forceinline__ void gemm49(const float* __restrict__ A, const float* __restrict__ W,
                                       const float* __restrict__ bias_g, float mult,
                                       float* __restrict__ out, int tid)
{
    const int warp = tid >> 5, lane = tid & 31;
    const int rg = warp >> 1;                       // 8 row groups of 7 rows
    const int d0 = ((warp & 1) << 6) + (lane << 1); // 2 output cols per thread
    const int n0 = rg * 7;
    const int sw = ((d0 >> 1) & 7) << 2;            // same for d0 and d0+1 (d0 even)
    const float* w0 = W + (d0 << 7);
    const float* w1 = W + ((d0 + 1) << 7);
    const float* a0 = A + (n0 << 7);

    unsigned long long acc[7][2];
    #pragma unroll
    for (int ii = 0; ii < 7; ii++) { acc[ii][0] = 0ull; acc[ii][1] = 0ull; }

    #pragma unroll 4
    for (int k = 0; k < 128; k += 4) {
        const int kc = k ^ sw;
        ulonglong2 wv0 = *(const ulonglong2*)(w0 + kc);
        ulonglong2 wv1 = *(const ulonglong2*)(w1 + kc);
        ulonglong2 av[7];
        #pragma unroll
        for (int ii = 0; ii < 7; ii++)
            av[ii] = *(const ulonglong2*)(a0 + (ii << 7) + k);
        #pragma unroll
        for (int ii = 0; ii < 7; ii++) {
            fma2(acc[ii][0], av[ii].x, wv0.x);
            fma2(acc[ii][0], av[ii].y, wv0.y);
            fma2(acc[ii][1], av[ii].x, wv1.x);
            fma2(acc[ii][1], av[ii].y, wv1.y);
        }
    }
    const float b0 = bias_g[d0], b1 = bias_g[d0 + 1];
    #pragma unroll
    for (int ii = 0; ii < 7; ii++) {
        int n = n0 + ii;
        if (n < TOK) {
            float2 p0 = unpk(acc[ii][0]);
            float2 p1 = unpk(acc[ii][1]);
            float2 r;
            r.x = (p0.x + p0.y + b0) * mult;
            r.y = (p1.x + p1.y + b1) * mult;
            if (TO_GLOBAL) *(float2*)&out[(n << 7) + d0] = r;
            else           *(float2*)&out[(n << 7) + (d0 ^ ((n & 7) << 2))] = r;
        }
    }
}

__global__ void __launch_bounds__(THREADS, 1)
win_attn_kernel(const float* __restrict__ x, const float* __restrict__ mask,
                const float* __restrict__ qkv_w, const float* __restrict__ qkv_b,
                const float* __restrict__ proj_w, const float* __restrict__ proj_b,
                const float* __restrict__ rpb, const int* __restrict__ rpi,
                float* __restrict__ out)
{
    extern __shared__ float sm[];
    float* xs = sm + XS_OFF;
    float* qs = sm + QS_OFF;
    float* ks = sm + KS_OFF;
    float* vs = sm + VS_OFF;
    float* ws = sm + WS_OFF;
    int*   rpis = (int*)(sm + RPI_OFF);
    float* rpbs = sm + RPB_OFF;

    const int tid = threadIdx.x;
    const int b = blockIdx.x;
    const float* xb = x + (size_t)b * (TOK * 128);

    // ---- phase 1: stage x, rpi, rpb ----
    for (int i = tid * 4; i < TOK * 128; i += THREADS * 4)
        *(float4*)&xs[i] = *(const float4*)(xb + i);
    for (int i = tid; i < 2401; i += THREADS) rpis[i] = rpi[i];
    for (int i = tid; i < 676; i += THREADS) rpbs[i] = rpb[i];
    __syncthreads();

    // ---- phase 2: qkv = x @ qkv_w^T + b   (q pre-scaled) ----
    const float scale = 0.17677669529663687f;  // (DIM/HEADS)^-0.5 = 32^-0.5
    float* dst[3] = {qs, ks, vs};
    #pragma unroll
    for (int cc = 0; cc < 3; cc++) {
        load_wchunk(qkv_w + cc * 16384, ws, tid);
        __syncthreads();
        gemm49<false>(xs, ws, qkv_b + cc * 128, cc == 0 ? scale : 1.0f, dst[cc], tid);
        __syncthreads();
    }

    // ---- phase 3: scores s[h][i][j] = q.k + bias + mask ----
    float* s = ws;                                     // 4*49*49 = 9604 <= 16384
    const float* maskw = mask + (size_t)(b & 255) * 2401;
    {
        const int warp = tid >> 5, lane = tid & 31;
        for (int row = warp; row < 196; row += 16) {   // row = h*49 + i
            const int h = row / 49;
            const int i = row - h * 49;
            const int swq = (i & 7) << 2;
            const int hb = h << 5;
            ulonglong2 qv[8];
            #pragma unroll
            for (int t = 0; t < 8; t++)
                qv[t] = *(const ulonglong2*)&qs[(i << 7) + hb + ((t << 2) ^ swq)];
            const int j0 = lane, j1 = lane + 32;
            const int swk = (lane & 7) << 2;           // same for j0 and j1
            unsigned long long acc0 = 0ull, acc1 = 0ull;
            #pragma unroll
            for (int t = 0; t < 8; t++) {
                int off = hb + ((t << 2) ^ swk);
                ulonglong2 k0 = *(const ulonglong2*)&ks[(j0 << 7) + off];
                ulonglong2 k1 = *(const ulonglong2*)&ks[(j1 << 7) + off];
                fma2(acc0, qv[t].x, k0.x); fma2(acc0, qv[t].y, k0.y);
                fma2(acc1, qv[t].x, k1.x); fma2(acc1, qv[t].y, k1.y);
            }
            {
                float2 p = unpk(acc0);
                int rem = i * 49 + j0;
                s[row * 49 + j0] = p.x + p.y + rpbs[(rpis[rem] << 2) + h] + maskw[rem];
            }
            if (j1 < TOK) {
                float2 p = unpk(acc1);
                int rem = i * 49 + j1;
                s[row * 49 + j1] = p.x + p.y + rpbs[(rpis[rem] << 2) + h] + maskw[rem];
            }
        }
    }
    __syncthreads();

    // ---- phase 4: softmax over j, in place ----
    if (tid < 196) {
        float* sr = s + tid * 49;
        float m = -1e30f;
        #pragma unroll 7
        for (int j = 0; j < TOK; j++) m = fmaxf(m, sr[j]);
        float sum = 0.f;
        #pragma unroll 7
        for (int j = 0; j < TOK; j++) { float e = __expf(sr[j] - m); sr[j] = e; sum += e; }
        float inv = __fdividef(1.0f, sum);
        #pragma unroll 7
        for (int j = 0; j < TOK; j++) sr[j] *= inv;
    }
    __syncthreads();

    // ---- phase 5: ao[n][h*32+e] = sum_j s[h][n][j] * v[j][h*32+e]  (ao reuses xs) ----
    float* ao = xs;
    {
        const int warp = tid >> 5, lane = tid & 31;
        const int rg = warp >> 1;                      // 8 row groups of 7 rows
        const int d0 = ((warp & 1) << 6) + (lane << 1);
        const int h = d0 >> 5;
        const int n0 = rg * 7;
        const float* sh = s + h * 2401;
        float acc[7][2];
        #pragma unroll
        for (int ii = 0; ii < 7; ii++) { acc[ii][0] = 0.f; acc[ii][1] = 0.f; }
        for (int j = 0; j < TOK; j++) {
            float2 vv = *(const float2*)&vs[(j << 7) + (d0 ^ ((j & 7) << 2))];
            float sv[7];
            #pragma unroll
            for (int ii = 0; ii < 7; ii++) sv[ii] = sh[(n0 + ii) * 49 + j];
            #pragma unroll
            for (int ii = 0; ii < 7; ii++) {
                acc[ii][0] += sv[ii] * vv.x;
                acc[ii][1] += sv[ii] * vv.y;
            }
        }
        #pragma unroll
        for (int ii = 0; ii < 7; ii++) {
            int n = n0 + ii;
            if (n < TOK) {
                ao[(n << 7) + d0]     = acc[ii][0];
                ao[(n << 7) + d0 + 1] = acc[ii][1];
            }
        }
    }
    __syncthreads();

    // ---- phase 6: out = ao @ proj_w^T + proj_b ----
    load_wchunk(proj_w, ws, tid);
    __syncthreads();
    gemm49<true>(ao, ws, proj_b, 1.0f, out + (size_t)b * (TOK * 128), tid);
}

extern "C" void kernel_launch(void* const* d_in, const int* in_sizes, int n_in,
                              void* d_out, int out_size) {
    const float* x      = (const float*)d_in[0];
    const float* mask   = (const float*)d_in[1];
    const float* qkv_w  = (const float*)d_in[2];
    const float* qkv_b  = (const float*)d_in[3];
    const float* proj_w = (const float*)d_in[4];
    const float* proj_b = (const float*)d_in[5];
    const float* rpb    = (const float*)d_in[6];
    const int*   rpi    = (const int*)d_in[7];
    float* out = (float*)d_out;

    int nwin = in_sizes[0] / (TOK * 128);
    cudaFuncSetAttribute(win_attn_kernel, cudaFuncAttributeMaxDynamicSharedMemorySize, SMEM_BYTES);
    win_attn_kernel<<<nwin, THREADS, SMEM_BYTES>>>(x, mask, qkv_w, qkv_b, proj_w, proj_b, rpb, rpi, out);
}

// round 13
// speedup vs baseline: 1.0009x; 1.0009x over previous
#include <cuda_runtime.h>

// Swin window attention, fused per-window. 512 threads/CTA (16 warps) for
// latency hiding; all intermediates in smem.
// Inputs (metadata order): x[16384*49*128] f32, mask[256*49*49] f32,
// qkv_w[384*128] f32, qkv_b[384] f32, proj_w[128*128] f32, proj_b[128] f32,
// rpb_table[169*4] f32, rpi[49*49] i32.  Output: [16384*49*128] f32.

#define TOK 49
constexpr int THREADS = 512;

// smem layout (float offsets)
constexpr int XS_OFF  = 0;            // x (49x128), later attention output
constexpr int QS_OFF  = 6272;         // q pre-scaled, row-swizzled
constexpr int KS_OFF  = 12544;
constexpr int VS_OFF  = 18816;
constexpr int WS_OFF  = 25088;        // 128x128 weight chunk (swizzled); reused for scores (4*49*49)
constexpr int RPI_OFF = 41472;        // 2401 int32
constexpr int RPB_OFF = 43873;        // 676 f32
constexpr int SMEM_FLOATS = 44549;
constexpr int SMEM_BYTES  = SMEM_FLOATS * 4;   // 178196 B

__device__ __forceinline__ void fma2(unsigned long long& d, unsigned long long a, unsigned long long b) {
    asm("fma.rn.f32x2 %0, %1, %2, %0;" : "+l"(d) : "l"(a), "l"(b));
}
__device__ __forceinline__ float2 unpk(unsigned long long v) {
    float2 r; asm("mov.b64 {%0, %1}, %2;" : "=f"(r.x), "=f"(r.y) : "l"(v)); return r;
}

// copy a 128x128 f32 weight block (row d contiguous over c) into ws with an
// XOR-4 swizzle so that column-strided LDS.128 reads are bank-conflict-free.
__device__ __forceinline__ void load_wchunk(const float* __restrict__ g, float* ws, int tid) {
    for (int i = tid * 4; i < 16384; i += THREADS * 4) {
        float4 v = *(const float4*)(g + i);
        int d = i >> 7, c = i & 127;
        *(float4*)&ws[(d << 7) + (c ^ (((d >> 1) & 7) << 2))] = v;
    }
}

// out[n][d] = (sum_c A[n][c] * W[d][c] + bias[d]) * mult, n in [0,49), d in [0,128)
// 16 warps: 8 row groups of 7 rows x 2 column halves. 2 output cols per thread.
// A: smem, stride 128, unswizzled.  W: ws (swizzled per load_wchunk).
// TO_GLOBAL: store contiguous to global; else store to smem with row XOR swizzle.
template<bool TO_GLOBAL>
__device__ __forceinline__ void gemm49(const float* __restrict__ A, const float* __restrict__ W,
                                       const float* __restrict__ bias_g, float mult,
                                       float* __restrict__ out, int tid)
{
    const int warp = tid >> 5, lane = tid & 31;
    const int rg = warp >> 1;                       // 8 row groups of 7 rows
    const int d0 = ((warp & 1) << 6) + (lane << 1); // 2 output cols per thread
    const int n0 = rg * 7;
    const int sw = ((d0 >> 1) & 7) << 2;            // same for d0 and d0+1 (d0 even)
    const float* w0 = W + (d0 << 7);
    const float* w1 = W + ((d0 + 1) << 7);
    const float* a0 = A + (n0 << 7);

    unsigned long long acc[7][2];
    #pragma unroll
    for (int ii = 0; ii < 7; ii++) { acc[ii][0] = 0ull; acc[ii][1] = 0ull; }

    #pragma unroll 4
    for (int k = 0; k < 128; k += 4) {
        const int kc = k ^ sw;
        ulonglong2 wv0 = *(const ulonglong2*)(w0 + kc);
        ulonglong2 wv1 = *(const ulonglong2*)(w1 + kc);
        ulonglong2 av[7];
        #pragma unroll
        for (int ii = 0; ii < 7; ii++)
            av[ii] = *(const ulonglong2*)(a0 + (ii << 7) + k);
        #pragma unroll
        for (int ii = 0; ii < 7; ii++) {
            fma2(acc[ii][0], av[ii].x, wv0.x);
            fma2(acc[ii][0], av[ii].y, wv0.y);
            fma2(acc[ii][1], av[ii].x, wv1.x);
            fma2(acc[ii][1], av[ii].y, wv1.y);
        }
    }
    const float b0 = bias_g[d0], b1 = bias_g[d0 + 1];
    #pragma unroll
    for (int ii = 0; ii < 7; ii++) {
        int n = n0 + ii;
        if (n < TOK) {
            float2 p0 = unpk(acc[ii][0]);
            float2 p1 = unpk(acc[ii][1]);
            float2 r;
            r.x = (p0.x + p0.y + b0) * mult;
            r.y = (p1.x + p1.y + b1) * mult;
            if (TO_GLOBAL) *(float2*)&out[(n << 7) + d0] = r;
            else           *(float2*)&out[(n << 7) + (d0 ^ ((n & 7) << 2))] = r;
        }
    }
}

__global__ void __launch_bounds__(THREADS, 1)
win_attn_kernel(const float* __restrict__ x, const float* __restrict__ mask,
                const float* __restrict__ qkv_w, const float* __restrict__ qkv_b,
                const float* __restrict__ proj_w, const float* __restrict__ proj_b,
                const float* __restrict__ rpb, const int* __restrict__ rpi,
                float* __restrict__ out)
{
    extern __shared__ float sm[];
    float* xs = sm + XS_OFF;
    float* qs = sm + QS_OFF;
    float* ks = sm + KS_OFF;
    float* vs = sm + VS_OFF;
    float* ws = sm + WS_OFF;
    int*   rpis = (int*)(sm + RPI_OFF);
    float* rpbs = sm + RPB_OFF;

    const int tid = threadIdx.x;
    const int b = blockIdx.x;
    const float* xb = x + (size_t)b * (TOK * 128);

    // ---- phase 1: stage x, rpi, rpb ----
    for (int i = tid * 4; i < TOK * 128; i += THREADS * 4)
        *(float4*)&xs[i] = *(const float4*)(xb + i);
    for (int i = tid; i < 2401; i += THREADS) rpis[i] = rpi[i];
    for (int i = tid; i < 676; i += THREADS) rpbs[i] = rpb[i];
    __syncthreads();

    // ---- phase 2: qkv = x @ qkv_w^T + b   (q pre-scaled) ----
    const float scale = 0.17677669529663687f;  // (DIM/HEADS)^-0.5 = 32^-0.5
    float* dst[3] = {qs, ks, vs};
    #pragma unroll
    for (int cc = 0; cc < 3; cc++) {
        load_wchunk(qkv_w + cc * 16384, ws, tid);
        __syncthreads();
        gemm49<false>(xs, ws, qkv_b + cc * 128, cc == 0 ? scale : 1.0f, dst[cc], tid);
        __syncthreads();
    }

    // ---- phase 3: scores s[h][i][j] = q.k + bias + mask ----
    float* s = ws;                                     // 4*49*49 = 9604 <= 16384
    const float* maskw = mask + (size_t)(b & 255) * 2401;
    {
        const int warp = tid >> 5, lane = tid & 31;
        for (int row = warp; row < 196; row += 16) {   // row = h*49 + i
            const int h = row / 49;
            const int i = row - h * 49;
            const int swq = (i & 7) << 2;
            const int hb = h << 5;
            ulonglong2 qv[8];
            #pragma unroll
            for (int t = 0; t < 8; t++)
                qv[t] = *(const ulonglong2*)&qs[(i << 7) + hb + ((t << 2) ^ swq)];
            const int j0 = lane, j1 = lane + 32;
            const int swk = (lane & 7) << 2;           // same for j0 and j1
            unsigned long long acc0 = 0ull, acc1 = 0ull;
            #pragma unroll
            for (int t = 0; t < 8; t++) {
                int off = hb + ((t << 2) ^ swk);
                ulonglong2 k0 = *(const ulonglong2*)&ks[(j0 << 7) + off];
                ulonglong2 k1 = *(const ulonglong2*)&ks[(j1 << 7) + off];
                fma2(acc0, qv[t].x, k0.x); fma2(acc0, qv[t].y, k0.y);
                fma2(acc1, qv[t].x, k1.x); fma2(acc1, qv[t].y, k1.y);
            }
            {
                float2 p = unpk(acc0);
                int rem = i * 49 + j0;
                s[row * 49 + j0] = p.x + p.y + rpbs[(rpis[rem] << 2) + h] + maskw[rem];
            }
            if (j1 < TOK) {
                float2 p = unpk(acc1);
                int rem = i * 49 + j1;
                s[row * 49 + j1] = p.x + p.y + rpbs[(rpis[rem] << 2) + h] + maskw[rem];
            }
        }
    }
    __syncthreads();

    // ---- phase 4: softmax over j, in place ----
    if (tid < 196) {
        float* sr = s + tid * 49;
        float m = -1e30f;
        #pragma unroll 7
        for (int j = 0; j < TOK; j++) m = fmaxf(m, sr[j]);
        float sum = 0.f;
        #pragma unroll 7
        for (int j = 0; j < TOK; j++) { float e = __expf(sr[j] - m); sr[j] = e; sum += e; }
        float inv = __fdividef(1.0f, sum);
        #pragma unroll 7
        for (int j = 0; j < TOK; j++) sr[j] *= inv;
    }
    __syncthreads();

    // ---- phase 5: ao[n][h*32+e] = sum_j s[h][n][j] * v[j][h*32+e]  (ao reuses xs) ----
    float* ao = xs;
    {
        const int warp = tid >> 5, lane = tid & 31;
        const int rg = warp >> 1;                      // 8 row groups of 7 rows
        const int d0 = ((warp & 1) << 6) + (lane << 1);
        const int h = d0 >> 5;
        const int n0 = rg * 7;
        const float* sh = s + h * 2401;
        float acc[7][2];
        #pragma unroll
        for (int ii = 0; ii < 7; ii++) { acc[ii][0] = 0.f; acc[ii][1] = 0.f; }
        for (int j = 0; j < TOK; j++) {
            float2 vv = *(const float2*)&vs[(j << 7) + (d0 ^ ((j & 7) << 2))];
            float sv[7];
            #pragma unroll
            for (int ii = 0; ii < 7; ii++) sv[ii] = sh[(n0 + ii) * 49 + j];
            #pragma unroll
            for (int ii = 0; ii < 7; ii++) {
                acc[ii][0] += sv[ii] * vv.x;
                acc[ii][1] += sv[ii] * vv.y;
            }
        }
        #pragma unroll
        for (int ii = 0; ii < 7; ii++) {
            int n = n0 + ii;
            if (n < TOK) {
                ao[(n << 7) + d0]     = acc[ii][0];
                ao[(n << 7) + d0 + 1] = acc[ii][1];
            }
        }
    }
    __syncthreads();

    // ---- phase 6: out = ao @ proj_w^T + proj_b ----
    load_wchunk(proj_w, ws, tid);
    __syncthreads();
    gemm49<true>(ao, ws, proj_b, 1.0f, out + (size_t)b * (TOK * 128), tid);
}

extern "C" void kernel_launch(void* const* d_in, const int* in_sizes, int n_in,
                              void* d_out, int out_size) {
    const float* x      = (const float*)d_in[0];
    const float* mask   = (const float*)d_in[1];
    const float* qkv_w  = (const float*)d_in[2];
    const float* qkv_b  = (const float*)d_in[3];
    const float* proj_w = (const float*)d_in[4];
    const float* proj_b = (const float*)d_in[5];
    const float* rpb    = (const float*)d_in[6];
    const int*   rpi    = (const int*)d_in[7];
    float* out = (float*)d_out;

    int nwin = in_sizes[0] / (TOK * 128);
    cudaFuncSetAttribute(win_attn_kernel, cudaFuncAttributeMaxDynamicSharedMemorySize, SMEM_BYTES);
    win_attn_kernel<<<nwin, THREADS, SMEM_BYTES>>>(x, mask, qkv_w, qkv_b, proj_w, proj_b, rpb, rpi, out);
}